// round 16
// baseline (speedup 1.0000x reference)
#include <cuda_runtime.h>
#include <cuda_bf16.h>

#define NB 8
#define NPTS 16384
#define NQ 1024
#define NC 64
#define NS 32
#define R2 0.04f

// 2 MB scratch: xyz packed as float4 for single-LDG.128 scan loads.
__device__ float4 g_xyz4[(size_t)NB * NPTS];
// 33.5 MB scratch: features transposed to (B, N, C); fits in L2 (126 MB).
__device__ float g_feats_t[(size_t)NB * NPTS * NC];

#define TBLOCKS (NB * (NPTS / 32))      // 4096 transpose tiles
#define PBLOCKS ((NB * NPTS) / 256)     // 512 pack blocks

// ---- fused pre-pass: feats transpose + xyz pack (job by blockIdx.x) ----
__global__ __launch_bounds__(256) void prepass_kernel(
    const float* __restrict__ xyz, const float* __restrict__ feats)
{
    if (blockIdx.x < TBLOCKS) {
        __shared__ float tile[32][65];
        const int b  = blockIdx.x >> 9;          // / (NPTS/32)
        const int n0 = (blockIdx.x & 511) * 32;
        const int t  = threadIdx.x;
        const int tx = t & 31;
        const int ty = t >> 5;

        const float* src = feats + (size_t)b * NC * NPTS + n0;
        #pragma unroll
        for (int k = 0; k < 8; ++k) {
            const int c = ty * 8 + k;
            tile[tx][c] = src[(size_t)c * NPTS + tx];
        }
        __syncthreads();

        float* dst = g_feats_t + ((size_t)b * NPTS + n0) * NC;
        #pragma unroll
        for (int k = 0; k < 8; ++k) {
            const int idx = k * 256 + t;
            const int n = idx >> 6;
            const int c = idx & 63;
            dst[(size_t)n * NC + c] = tile[n][c];
        }
    } else {
        __shared__ float sbuf[8][96];
        const int bid  = blockIdx.x - TBLOCKS;
        const int warp = threadIdx.x >> 5, lane = threadIdx.x & 31;
        const size_t base = (size_t)bid * 256 + warp * 32;
        const float* src = xyz + base * 3;
        float* s = sbuf[warp];
        s[lane]      = src[lane];
        s[lane + 32] = src[lane + 32];
        s[lane + 64] = src[lane + 64];
        __syncwarp();
        g_xyz4[base + lane] = make_float4(s[lane * 3], s[lane * 3 + 1], s[lane * 3 + 2], 0.f);
    }
}

#define FSTRIDE 68     // fsm row stride in floats: conflict-free STS.128/LDS.128
#define REGION 4096    // NPTS / 4 points per warp

// ---- main: one block per query; barrier-free per-warp region scan ----
__global__ __launch_bounds__(128) void qag_kernel(
    const float* __restrict__ new_xyz,  // (B, S, 3)
    float* __restrict__ out)            // (B, 3+C, S, NS)
{
    const int lane = threadIdx.x & 31;
    const int w    = threadIdx.x >> 5;         // warp id 0..3
    const int q = blockIdx.x;                  // one query per block
    const int b = q >> 10;                     // / NQ
    const int s = q & (NQ - 1);

    __shared__ __align__(16) float fsm[NS * FSTRIDE];   // [sample][channel]
    __shared__ __align__(16) int   wbuf[4][NS + 256];   // per-warp hit lists (slack)
    __shared__ int idx32[NS];                  // merged + padded indices
    __shared__ int wcnts[4];
    __shared__ int flagword;                   // bit w: warp w reached 32 hits

    if (threadIdx.x == 0) flagword = 0;
    __syncthreads();

    const float qx = new_xyz[q * 3 + 0];
    const float qy = new_xyz[q * 3 + 1];
    const float qz = new_xyz[q * 3 + 2];

    const float4* __restrict__ xb4 = g_xyz4 + (size_t)b * NPTS;
    const unsigned lt = (1u << lane) - 1u;
    const unsigned lower = (1u << w) - 1u;     // mask of lower-warp flags

    // ---- scan own region [w*4096, +4096) in 256-pt rounds, NO block barriers ----
    int wcnt = 0;
    const int rbase = w * REGION;
    for (int j0 = 0; j0 < REGION; j0 += 256) {
        if (w > 0 && (*(volatile int*)&flagword & lower)) break;  // unused if set

        float4 p[8];
        #pragma unroll
        for (int u = 0; u < 8; ++u) p[u] = xb4[rbase + j0 + u * 32 + lane];

        bool wi[8];
        #pragma unroll
        for (int u = 0; u < 8; ++u) {
            const float dx = p[u].x - qx;
            const float dy = p[u].y - qy;
            const float dz = p[u].z - qz;
            wi[u] = dx * dx + dy * dy + dz * dz < R2;
        }
        unsigned m[8];
        #pragma unroll
        for (int u = 0; u < 8; ++u) m[u] = __ballot_sync(0xFFFFFFFFu, wi[u]);

        int base = wcnt;
        #pragma unroll
        for (int u = 0; u < 8; ++u) {
            if (wi[u]) wbuf[w][base + __popc(m[u] & lt)] = rbase + j0 + u * 32 + lane;
            base += __popc(m[u]);
        }
        wcnt = base;
        if (wcnt >= NS) {                      // region's first 32 secured
            if (lane == 0) atomicOr(&flagword, 1 << w);
            break;
        }
    }
    if (lane == 0) wcnts[w] = wcnt < NS ? wcnt : NS;
    __syncthreads();

    // ---- merge: warp 0 concatenates region lists in warp order ----
    if (w == 0) {
        const int c0 = wcnts[0], c1 = wcnts[1], c2 = wcnts[2], c3 = wcnts[3];
        const int t1 = c0 + c1, t2 = t1 + c2, t3 = t2 + c3;
        const int eff = t3 < NS ? t3 : NS;
        int v = 0;
        if      (lane < c0) v = wbuf[0][lane];
        else if (lane < t1) v = wbuf[1][lane - c0];
        else if (lane < t2) v = wbuf[2][lane - t1];
        else if (lane < t3) v = wbuf[3][lane - t2];
        const int first = __shfl_sync(0xFFFFFFFFu, v, 0);  // 0 when eff==0
        if (lane >= eff) v = first;            // pad with first valid (0 if none)
        idx32[lane] = v;
    }
    __syncthreads();

    const size_t CH = (size_t)NQ * NS;
    float* ob = out + ((size_t)b * (3 + NC) * NQ + s) * NS + lane;

    // ---- grouped xyz (warp 0 only), coalesced writes ----
    if (w == 0) {
        const float4 P = xb4[idx32[lane]];
        ob[0 * CH] = P.x - qx;
        ob[1 * CH] = P.y - qy;
        ob[2 * CH] = P.z - qz;
    }

    // ---- grouped features: half-warp per sample row -> fsm via STS.128 ----
    {
        const float4* __restrict__ fbase =
            (const float4*)(g_feats_t + (size_t)b * NPTS * NC);
        const int g    = lane & 15;
        const int half = lane >> 4;
        #pragma unroll
        for (int i = 0; i < 4; ++i) {
            const int msamp = 8 * w + 2 * i + half;
            const int im = idx32[msamp];
            const float4 v = __ldg(fbase + (size_t)im * (NC / 4) + g);
            *(float4*)&fsm[msamp * FSTRIDE + 4 * g] = v;   // STS.128, conflict-free
        }
    }
    __syncthreads();

    // ---- writeout: warp w covers channels 16w..16w+15 via LDS.128, lane=sample ----
    float* of = ob + 3 * CH;
    #pragma unroll
    for (int c4 = 0; c4 < 4; ++c4) {
        const int ch0 = 16 * w + 4 * c4;
        const float4 fv = *(const float4*)&fsm[lane * FSTRIDE + ch0];  // LDS.128
        of[(size_t)(ch0 + 0) * CH] = fv.x;
        of[(size_t)(ch0 + 1) * CH] = fv.y;
        of[(size_t)(ch0 + 2) * CH] = fv.z;
        of[(size_t)(ch0 + 3) * CH] = fv.w;
    }
}

extern "C" void kernel_launch(void* const* d_in, const int* in_sizes, int n_in,
                              void* d_out, int out_size) {
    const float* xyz     = (const float*)d_in[0];
    const float* new_xyz = (const float*)d_in[1];
    const float* feats   = (const float*)d_in[2];
    float* out = (float*)d_out;

    prepass_kernel<<<TBLOCKS + PBLOCKS, 256>>>(xyz, feats);

    qag_kernel<<<NB * NQ, 128>>>(new_xyz, out);   // one block per query
}

// round 17
// speedup vs baseline: 1.4968x; 1.4968x over previous
#include <cuda_runtime.h>
#include <cuda_bf16.h>

#define NB 8
#define NPTS 16384
#define NQ 1024
#define NC 64
#define NS 32
#define R2 0.04f
#define QTH 2780      // conservative int threshold for u8-quantized prefilter

// 2 MB scratch: xyz packed as float4 for exact-test LDG.128 loads.
__device__ float4 g_xyz4[(size_t)NB * NPTS];
// 0.5 MB scratch: xyz quantized to u8x3 in one uint32 for the prefilter.
__device__ unsigned g_xyzq[(size_t)NB * NPTS];
// 33.5 MB scratch: features transposed to (B, N, C); fits in L2 (126 MB).
__device__ float g_feats_t[(size_t)NB * NPTS * NC];

#define TBLOCKS (NB * (NPTS / 32))      // 4096 transpose tiles
#define PBLOCKS ((NB * NPTS) / 256)     // 512 pack blocks

// ---- fused pre-pass: feats transpose + xyz pack/quantize ----
__global__ __launch_bounds__(256) void prepass_kernel(
    const float* __restrict__ xyz, const float* __restrict__ feats)
{
    if (blockIdx.x < TBLOCKS) {
        __shared__ float tile[32][65];
        const int b  = blockIdx.x >> 9;          // / (NPTS/32)
        const int n0 = (blockIdx.x & 511) * 32;
        const int t  = threadIdx.x;
        const int tx = t & 31;
        const int ty = t >> 5;

        const float* src = feats + (size_t)b * NC * NPTS + n0;
        #pragma unroll
        for (int k = 0; k < 8; ++k) {
            const int c = ty * 8 + k;
            tile[tx][c] = src[(size_t)c * NPTS + tx];
        }
        __syncthreads();

        float* dst = g_feats_t + ((size_t)b * NPTS + n0) * NC;
        #pragma unroll
        for (int k = 0; k < 8; ++k) {
            const int idx = k * 256 + t;
            const int n = idx >> 6;
            const int c = idx & 63;
            dst[(size_t)n * NC + c] = tile[n][c];
        }
    } else {
        __shared__ float sbuf[8][96];
        const int bid  = blockIdx.x - TBLOCKS;
        const int warp = threadIdx.x >> 5, lane = threadIdx.x & 31;
        const size_t base = (size_t)bid * 256 + warp * 32;
        const float* src = xyz + base * 3;
        float* s = sbuf[warp];
        s[lane]      = src[lane];
        s[lane + 32] = src[lane + 32];
        s[lane + 64] = src[lane + 64];
        __syncwarp();
        const float px = s[lane * 3], py = s[lane * 3 + 1], pz = s[lane * 3 + 2];
        g_xyz4[base + lane] = make_float4(px, py, pz, 0.f);
        const unsigned ux = (unsigned)(px * 255.f + 0.5f);
        const unsigned uy = (unsigned)(py * 255.f + 0.5f);
        const unsigned uz = (unsigned)(pz * 255.f + 0.5f);
        g_xyzq[base + lane] = ux | (uy << 8) | (uz << 16);
    }
}

#define FSTRIDE 68   // fsm row stride in floats: conflict-free STS.128/LDS.128

// ---- main: one block (4 warps) per query; prefiltered 1024-pt rounds ----
__global__ __launch_bounds__(128) void qag_kernel(
    const float* __restrict__ new_xyz,  // (B, S, 3)
    float* __restrict__ out)            // (B, 3+C, S, NS)
{
    const int lane = threadIdx.x & 31;
    const int w    = threadIdx.x >> 5;         // warp id 0..3
    const int q = blockIdx.x;                  // one query per block
    const int b = q >> 10;                     // / NQ
    const int s = q & (NQ - 1);

    __shared__ __align__(16) float fsm[NS * FSTRIDE];   // [sample][channel]
    __shared__ __align__(16) int   idx_buf[NS + 1024];  // unchecked appends
    __shared__ int wtot[2][4];                 // double-buffered per-warp counts

    const float qx = new_xyz[q * 3 + 0];
    const float qy = new_xyz[q * 3 + 1];
    const float qz = new_xyz[q * 3 + 2];

    // quantized query (independent rounding is covered by the ±1/axis bound)
    const int qxq = (int)(qx * 255.f + 0.5f);
    const int qyq = (int)(qy * 255.f + 0.5f);
    const int qzq = (int)(qz * 255.f + 0.5f);
    const unsigned qpk = (unsigned)(qxq | (qyq << 8) | (qzq << 16));
    const int qn = qxq * qxq + qyq * qyq + qzq * qzq;

    const float4*   __restrict__ xb4 = g_xyz4 + (size_t)b * NPTS;
    const unsigned* __restrict__ xbq = g_xyzq + (size_t)b * NPTS;
    const unsigned lt = (1u << lane) - 1u;

    // ---- ball query: 1024-pt rounds, warp w owns sub-chunk [w*256, +256) ----
    int cnt = 0;
    int pb = 0;
    for (int j0 = 0; j0 < NPTS; j0 += 1024) {
        const int jw = j0 + w * 256;

        // prefilter: 8 x LDG.32 (1 wf each), dp4a distance, conservative accept
        unsigned pq[8];
        #pragma unroll
        for (int u = 0; u < 8; ++u) pq[u] = xbq[jw + u * 32 + lane];

        unsigned cbits = 0;
        #pragma unroll
        for (int u = 0; u < 8; ++u) {
            const int spp = __dp4a(pq[u], pq[u], 0u);
            const int spq = __dp4a(pq[u], qpk, 0u);
            const int d2i = spp + qn - 2 * spq;
            if (d2i <= QTH) cbits |= 1u << u;
        }

        // exact recheck for candidate lanes only (predicated LDG.128)
        unsigned ebits = 0;
        unsigned m[8];
        #pragma unroll
        for (int h = 0; h < 2; ++h) {
            float4 P[4];
            #pragma unroll
            for (int k = 0; k < 4; ++k) {
                const int u = h * 4 + k;
                P[k] = make_float4(0.f, 0.f, 0.f, 0.f);
                if ((cbits >> u) & 1u) P[k] = xb4[jw + u * 32 + lane];
            }
            #pragma unroll
            for (int k = 0; k < 4; ++k) {
                const int u = h * 4 + k;
                const float dx = P[k].x - qx;
                const float dy = P[k].y - qy;
                const float dz = P[k].z - qz;
                const bool ex = ((cbits >> u) & 1u) &&
                                (dx * dx + dy * dy + dz * dz < R2);
                m[u] = __ballot_sync(0xFFFFFFFFu, ex);
                if (ex) ebits |= 1u << u;
            }
        }

        int tot = 0;
        #pragma unroll
        for (int u = 0; u < 8; ++u) tot += __popc(m[u]);
        if (lane == 0) wtot[pb][w] = tot;
        __syncthreads();

        // warp's write base = carried count + counts of lower warps this round
        int base = cnt;
        #pragma unroll
        for (int ww = 0; ww < 4; ++ww) {
            const int t = wtot[pb][ww];
            if (ww < w) base += t;
            cnt += t;
        }
        #pragma unroll
        for (int u = 0; u < 8; ++u) {
            if ((ebits >> u) & 1u)
                idx_buf[base + __popc(m[u] & lt)] = jw + u * 32 + lane;
            base += __popc(m[u]);
        }
        pb ^= 1;                // next round uses the other wtot buffer
        if (cnt >= NS) break;   // uniform across block
    }
    __syncthreads();            // final-round idx_buf visible

    const int eff = cnt < NS ? cnt : NS;
    const int first = (eff > 0) ? idx_buf[0] : 0;

    const size_t CH = (size_t)NQ * NS;
    float* ob = out + ((size_t)b * (3 + NC) * NQ + s) * NS + lane;

    // ---- grouped xyz (warp 0 only), coalesced writes ----
    if (w == 0) {
        const int im = (lane < eff) ? idx_buf[lane] : first;
        const float4 P = xb4[im];
        ob[0 * CH] = P.x - qx;
        ob[1 * CH] = P.y - qy;
        ob[2 * CH] = P.z - qz;
    }

    // ---- grouped features: half-warp per sample row -> fsm via STS.128 ----
    {
        const float4* __restrict__ fbase =
            (const float4*)(g_feats_t + (size_t)b * NPTS * NC);
        const int g    = lane & 15;
        const int half = lane >> 4;
        #pragma unroll
        for (int i = 0; i < 4; ++i) {
            const int msamp = 8 * w + 2 * i + half;
            const int im = (msamp < eff) ? idx_buf[msamp] : first;
            const float4 v = __ldg(fbase + (size_t)im * (NC / 4) + g);
            *(float4*)&fsm[msamp * FSTRIDE + 4 * g] = v;   // STS.128
        }
    }
    __syncthreads();

    // ---- writeout: warp w covers channels 16w..16w+15 via LDS.128 ----
    float* of = ob + 3 * CH;
    #pragma unroll
    for (int c4 = 0; c4 < 4; ++c4) {
        const int ch0 = 16 * w + 4 * c4;
        const float4 fv = *(const float4*)&fsm[lane * FSTRIDE + ch0];
        of[(size_t)(ch0 + 0) * CH] = fv.x;
        of[(size_t)(ch0 + 1) * CH] = fv.y;
        of[(size_t)(ch0 + 2) * CH] = fv.z;
        of[(size_t)(ch0 + 3) * CH] = fv.w;
    }
}

extern "C" void kernel_launch(void* const* d_in, const int* in_sizes, int n_in,
                              void* d_out, int out_size) {
    const float* xyz     = (const float*)d_in[0];
    const float* new_xyz = (const float*)d_in[1];
    const float* feats   = (const float*)d_in[2];
    float* out = (float*)d_out;

    prepass_kernel<<<TBLOCKS + PBLOCKS, 256>>>(xyz, feats);

    qag_kernel<<<NB * NQ, 128>>>(new_xyz, out);   // one block per query
}